// round 5
// baseline (speedup 1.0000x reference)
#include <cuda_runtime.h>
#include <math.h>

#define TOTAL_NODES 4416   // 2 * 96 * 23
#define NBATCH 2
#define NL 96
#define NNN 23
#define DIM 64
#define H1 258
#define MD 32
#define CH 128
#define EIN 129
#define TJ 32
#define THREADS 256

// ---------------- scratch (device globals; no allocs allowed) ----------------
__device__ float g_f[2][TOTAL_NODES * DIM];
__device__ float g_c[2][TOTAL_NODES * 3];
__device__ float g_A[TOTAL_NODES * H1];
__device__ float g_B[TOTAL_NODES * H1];
__device__ float g_mi[TOTAL_NODES * MD];
__device__ float g_delta[TOTAL_NODES * 3];

__device__ __forceinline__ float siluf(float x) {
    return x / (1.0f + __expf(-x));
}

// ---------------- embedding ----------------
__global__ void embed_kernel(const int* __restrict__ tokens,
                             const float* __restrict__ cords,
                             const float* __restrict__ tok_emb,
                             const float* __restrict__ pos_emb) {
    int idx = blockIdx.x * blockDim.x + threadIdx.x;
    if (idx < TOTAL_NODES * DIM) {
        int node = idx / DIM;
        int d = idx - node * DIM;
        int n = node % NNN;
        int bl = node / NNN;          // b*96 + l
        int t = tokens[bl];
        int pos = (t != 1) ? (n + 2) : 1;
        g_f[0][idx] = tok_emb[t * DIM + d] + pos_emb[pos * DIM + d];
    }
    if (idx < TOTAL_NODES * 3) {
        g_c[0][idx] = cords[idx];
    }
}

// ---------------- per-node precompute: A = f*Wtop + b1, B = f*Wbot ----------------
// 32 nodes per block
__global__ void pre_kernel(const float* __restrict__ ew1,
                           const float* __restrict__ eb1,
                           int layer, int pin) {
    const float* W = ew1 + (size_t)layer * EIN * H1;
    const float* bb = eb1 + layer * H1;
    __shared__ float sf[32 * DIM];
    int n0 = blockIdx.x * 32;
    for (int idx = threadIdx.x; idx < 32 * DIM; idx += THREADS)
        sf[idx] = g_f[pin][n0 * DIM + idx];
    __syncthreads();
    for (int idx = threadIdx.x; idx < 32 * H1; idx += THREADS) {
        int jn = idx / H1;
        int t = idx - jn * H1;
        float a = bb[t];
        float b2 = 0.0f;
        const float* fj = &sf[jn * DIM];
#pragma unroll 8
        for (int k = 0; k < DIM; k++) {
            a  += fj[k] * W[k * H1 + t];
            b2 += fj[k] * W[(DIM + k) * H1 + t];
        }
        g_A[(size_t)(n0 + jn) * H1 + t] = a;
        g_B[(size_t)(n0 + jn) * H1 + t] = b2;
    }
}

// ---------------- fused edge kernel: one block per (graph,row) ----------------
// smem layout (floats):
// sA(258) swd(258) sw2(8256) seb2(32) scw1(4096) scb1(128) scw2(128)
// sh1(TJ*258) sm2(TJ*32) shc(TJ*128) srel(TJ*3) sdist(TJ) sinv(TJ) swv(TJ)
// smi(32) sdelta(4) sci(4)
#define ESM_FLOATS (258+258+8256+32+4096+128+128+(TJ*258)+(TJ*32)+(TJ*128)+(TJ*3)+TJ+TJ+TJ+32+4+4)

__global__ void edge_kernel(const float* __restrict__ ew1,
                            const float* __restrict__ ew2,
                            const float* __restrict__ eb2,
                            const float* __restrict__ cw1,
                            const float* __restrict__ cb1,
                            const float* __restrict__ cw2,
                            const float* __restrict__ cb2,
                            int layer, int pin, int phase) {
    extern __shared__ float sm[];
    float* sA    = sm;               // 258
    float* swd   = sA + H1;          // 258
    float* sw2   = swd + H1;         // 8256
    float* seb2  = sw2 + H1 * MD;    // 32
    float* scw1  = seb2 + MD;        // 4096
    float* scb1  = scw1 + MD * CH;   // 128
    float* scw2  = scb1 + CH;        // 128
    float* sh1   = scw2 + CH;        // TJ*258
    float* sm2   = sh1 + TJ * H1;    // TJ*32
    float* shc   = sm2 + TJ * MD;    // TJ*128
    float* srel  = shc + TJ * CH;    // TJ*3
    float* sdist = srel + TJ * 3;    // TJ
    float* sinv  = sdist + TJ;       // TJ
    float* swv   = sinv + TJ;        // TJ
    float* smi   = swv + TJ;         // 32
    float* sdelta= smi + MD;         // 4
    float* sci   = sdelta + 4;       // 4

    int tid = threadIdx.x;
    int r = blockIdx.x;
    int Nn, node_i, base, stride;
    if (phase == 0) {
        Nn = NNN;
        int g = r / NNN;
        base = g * NNN;
        stride = 1;
        node_i = r;
    } else {
        Nn = NL;
        int g = r / NL;
        int i = r - g * NL;
        int b = g / NNN;
        int n = g - b * NNN;
        base = b * (NL * NNN) + n;
        stride = NNN;
        node_i = base + i * NNN;
    }

    // load weights / row data into smem
    const float* W2g = ew2 + (size_t)layer * H1 * MD;
    for (int idx = tid; idx < H1 * MD; idx += THREADS) sw2[idx] = W2g[idx];
    const float* C1g = cw1 + (size_t)layer * MD * CH;
    for (int idx = tid; idx < MD * CH; idx += THREADS) scw1[idx] = C1g[idx];
    const float* Wdg = ew1 + (size_t)layer * EIN * H1 + (size_t)(2 * DIM) * H1;
    const float* Ag = &g_A[(size_t)node_i * H1];
    for (int idx = tid; idx < H1; idx += THREADS) {
        sA[idx] = Ag[idx];
        swd[idx] = Wdg[idx];
    }
    if (tid < MD)  seb2[tid] = eb2[layer * MD + tid];
    if (tid < CH)  { scb1[tid] = cb1[layer * CH + tid]; scw2[tid] = cw2[layer * CH + tid]; }
    if (tid < MD)  smi[tid] = 0.0f;
    if (tid < 3)   { sdelta[tid] = 0.0f; sci[tid] = g_c[pin][node_i * 3 + tid]; }
    float cb2v = cb2[layer];
    __syncthreads();

    for (int jt = 0; jt < Nn; jt += TJ) {
        // ---- distances ----
        if (tid < TJ) {
            int j = jt + tid;
            if (j < Nn) {
                int nj = base + j * stride;
                float rx = sci[0] - g_c[pin][nj * 3 + 0];
                float ry = sci[1] - g_c[pin][nj * 3 + 1];
                float rz = sci[2] - g_c[pin][nj * 3 + 2];
                float d = rx * rx + ry * ry + rz * rz;
                srel[tid * 3 + 0] = rx;
                srel[tid * 3 + 1] = ry;
                srel[tid * 3 + 2] = rz;
                sdist[tid] = d;
                sinv[tid] = 1.0f / fmaxf(sqrtf(d), 1e-8f);
            } else {
                srel[tid * 3 + 0] = 0.f; srel[tid * 3 + 1] = 0.f; srel[tid * 3 + 2] = 0.f;
                sdist[tid] = 0.f;
                sinv[tid] = 0.f;
            }
        }
        __syncthreads();

        // ---- h1 = silu(A[i] + B[j] + dist*wd) ----
        for (int idx = tid; idx < TJ * H1; idx += THREADS) {
            int j = idx / H1;
            int t = idx - j * H1;
            int jj = jt + j;
            float bv = 0.0f;
            if (jj < Nn) {
                int nj = base + jj * stride;
                bv = g_B[(size_t)nj * H1 + t];
            }
            float v = sA[t] + bv + sdist[j] * swd[t];
            sh1[idx] = siluf(v);
        }
        __syncthreads();

        // ---- m2 = silu(h1 @ ew2 + eb2)  (1024 outputs, one float4 quad/thread) ----
        {
            int j = tid >> 3;
            int t2 = (tid & 7) * 4;
            float4 acc = *(const float4*)&seb2[t2];
            const float* h = &sh1[j * H1];
#pragma unroll 4
            for (int k = 0; k < H1; k++) {
                float hk = h[k];
                float4 w = *(const float4*)&sw2[k * MD + t2];
                acc.x += hk * w.x; acc.y += hk * w.y;
                acc.z += hk * w.z; acc.w += hk * w.w;
            }
            float4 o;
            bool valid = (jt + j) < Nn;
            o.x = valid ? siluf(acc.x) : 0.f;
            o.y = valid ? siluf(acc.y) : 0.f;
            o.z = valid ? siluf(acc.z) : 0.f;
            o.w = valid ? siluf(acc.w) : 0.f;
            *(float4*)&sm2[j * MD + t2] = o;
        }
        __syncthreads();

        // ---- hc = silu(m2 @ cw1 + cb1)  (4096 outputs, float4 quads) ----
        for (int q = tid; q < TJ * CH / 4; q += THREADS) {
            int j = q >> 5;
            int u = (q & 31) * 4;
            float4 acc = *(const float4*)&scb1[u];
            const float* mm = &sm2[j * MD];
#pragma unroll
            for (int k = 0; k < MD; k++) {
                float mk = mm[k];
                float4 w = *(const float4*)&scw1[k * CH + u];
                acc.x += mk * w.x; acc.y += mk * w.y;
                acc.z += mk * w.z; acc.w += mk * w.w;
            }
            float4 o;
            o.x = siluf(acc.x); o.y = siluf(acc.y);
            o.z = siluf(acc.z); o.w = siluf(acc.w);
            *(float4*)&shc[j * CH + u] = o;
        }
        __syncthreads();

        // ---- w[j] = hc @ cw2 + cb2  (warp per 4 rows) ----
        {
            int w = tid >> 5;
            int lane = tid & 31;
            for (int jj2 = w; jj2 < TJ; jj2 += 8) {
                float p = 0.0f;
                const float* hh = &shc[jj2 * CH];
#pragma unroll
                for (int u = lane; u < CH; u += 32) p += hh[u] * scw2[u];
                p += __shfl_xor_sync(0xffffffffu, p, 16);
                p += __shfl_xor_sync(0xffffffffu, p, 8);
                p += __shfl_xor_sync(0xffffffffu, p, 4);
                p += __shfl_xor_sync(0xffffffffu, p, 2);
                p += __shfl_xor_sync(0xffffffffu, p, 1);
                if (lane == 0)
                    swv[jj2] = ((jt + jj2) < Nn) ? (p + cb2v) : 0.0f;
            }
        }
        __syncthreads();

        // ---- accumulate m_i and coordinate delta ----
        if (tid < MD) {
            float acc = 0.0f;
#pragma unroll
            for (int j = 0; j < TJ; j++) acc += sm2[j * MD + tid];
            smi[tid] += acc;
        }
        if (tid >= 32 && tid < 35) {
            int c = tid - 32;
            float acc = 0.0f;
#pragma unroll
            for (int j = 0; j < TJ; j++) acc += swv[j] * srel[j * 3 + c] * sinv[j];
            sdelta[c] += acc;
        }
        __syncthreads();
    }

    if (tid < MD) g_mi[(size_t)node_i * MD + tid] = smi[tid];
    if (tid < 3)  g_delta[node_i * 3 + tid] = sdelta[tid];
}

// ---------------- node update + coord update (32 nodes / block) ----------------
__global__ void node_kernel(const float* __restrict__ nw1,
                            const float* __restrict__ nb1,
                            const float* __restrict__ nw2,
                            const float* __restrict__ nb2,
                            const float* __restrict__ ln_b,
                            int layer, int pin) {
    __shared__ float sin_[32 * 96];
    __shared__ float sh[32 * 128];
    int n0 = blockIdx.x * 32;
    int pout = pin ^ 1;
    for (int idx = threadIdx.x; idx < 32 * 96; idx += THREADS) {
        int jn = idx / 96;
        int k = idx - jn * 96;
        sin_[idx] = (k < DIM) ? g_f[pin][(n0 + jn) * DIM + k]
                              : g_mi[(n0 + jn) * MD + (k - DIM)];
    }
    __syncthreads();
    const float* W1 = nw1 + (size_t)layer * 96 * 128;
    for (int idx = threadIdx.x; idx < 32 * 128; idx += THREADS) {
        int jn = idx >> 7;
        int u = idx & 127;
        float v = nb1[layer * 128 + u];
        const float* si = &sin_[jn * 96];
#pragma unroll 8
        for (int k = 0; k < 96; k++) v += si[k] * W1[k * 128 + u];
        sh[idx] = siluf(v);
    }
    __syncthreads();
    const float* W2 = nw2 + (size_t)layer * 128 * 64;
    for (int idx = threadIdx.x; idx < 32 * 64; idx += THREADS) {
        int jn = idx >> 6;
        int d = idx & 63;
        float o = nb2[layer * 64 + d];
        const float* hh = &sh[jn * 128];
#pragma unroll 8
        for (int k = 0; k < 128; k++) o += hh[k] * W2[k * 64 + d];
        g_f[pout][(n0 + jn) * DIM + d] = o + sin_[jn * 96 + d];
    }
    float scale = ln_b[layer] * (1.0f / 50.0f);
    for (int idx = threadIdx.x; idx < 32 * 3; idx += THREADS) {
        g_c[pout][n0 * 3 + idx] = g_c[pin][n0 * 3 + idx] + scale * g_delta[n0 * 3 + idx];
    }
}

// ---------------- final copy ----------------
__global__ void copy_out_kernel(float* __restrict__ out) {
    int idx = blockIdx.x * blockDim.x + threadIdx.x;
    if (idx < TOTAL_NODES * 3) out[idx] = g_c[0][idx];
}

extern "C" void kernel_launch(void* const* d_in, const int* in_sizes, int n_in,
                              void* d_out, int out_size) {
    const int*   tokens  = (const int*)  d_in[0];
    const float* cords   = (const float*)d_in[1];
    const float* tok_emb = (const float*)d_in[2];
    const float* pos_emb = (const float*)d_in[3];
    const float* ew1 = (const float*)d_in[4];
    const float* eb1 = (const float*)d_in[5];
    const float* ew2 = (const float*)d_in[6];
    const float* eb2 = (const float*)d_in[7];
    const float* cw1 = (const float*)d_in[8];
    const float* cb1 = (const float*)d_in[9];
    const float* cw2 = (const float*)d_in[10];
    const float* cb2 = (const float*)d_in[11];
    const float* nw1 = (const float*)d_in[12];
    const float* nb1 = (const float*)d_in[13];
    const float* nw2 = (const float*)d_in[14];
    const float* nb2 = (const float*)d_in[15];
    const float* ln_b = (const float*)d_in[17];
    float* out = (float*)d_out;

    static int attr_done = 0;
    (void)attr_done;
    cudaFuncSetAttribute(edge_kernel,
                         cudaFuncAttributeMaxDynamicSharedMemorySize,
                         ESM_FLOATS * (int)sizeof(float));

    embed_kernel<<<(TOTAL_NODES * DIM + THREADS - 1) / THREADS, THREADS>>>(
        tokens, cords, tok_emb, pos_emb);

    int pin = 0;
    for (int L = 0; L < 16; L++) {
        int phase = (L >> 2) & 1;  // 0-3:N-graphs, 4-7:l-graphs, 8-11:N, 12-15:l
        pre_kernel<<<TOTAL_NODES / 32, THREADS>>>(ew1, eb1, L, pin);
        edge_kernel<<<TOTAL_NODES, THREADS, ESM_FLOATS * (int)sizeof(float)>>>(
            ew1, ew2, eb2, cw1, cb1, cw2, cb2, L, pin, phase);
        node_kernel<<<TOTAL_NODES / 32, THREADS>>>(nw1, nb1, nw2, nb2, ln_b, L, pin);
        pin ^= 1;
    }
    // after 16 toggles pin == 0 again; final coords live in g_c[0]
    copy_out_kernel<<<(TOTAL_NODES * 3 + THREADS - 1) / THREADS, THREADS>>>(out);
}